// round 12
// baseline (speedup 1.0000x reference)
#include <cuda_runtime.h>

#define NB 64
#define NC 3
#define NH 96
#define NW 320
#define NHW (NH*NW)
#define K_TOP 50
#define GCAP 4608
#define CDIR 1024
#define SBUF 512
#define FCAP 512
#define THETA 0.99f
#define DET_TH 0.25f
#define PI_F 3.14159265f
#define NSTRIPS 3840          // strips of 8 px per channel
#define SUBS 3
#define SUBSTRIPS 1280        // 5 * 256
#define NT1 256
#define NT2 256

typedef unsigned long long ull;

// per-channel candidate lists (packed (f2k(v)<<32)|~idx) + counts
__device__ ull g_cand[NB*NC*GCAP];
__device__ int g_ccnt[NB*NC];

__device__ __forceinline__ unsigned f2k(float f){
    unsigned b = __float_as_uint(f);
    return (b & 0x80000000u) ? ~b : (b | 0x80000000u);
}
__device__ __forceinline__ float k2f(unsigned k){
    return (k & 0x80000000u) ? __uint_as_float(k ^ 0x80000000u) : __uint_as_float(~k);
}
__device__ __forceinline__ float max4(float4 v){
    return fmaxf(fmaxf(v.x, v.y), fmaxf(v.z, v.w));
}

// full 3x3 NMS test for one 8-pixel strip; bitmask of peaks > theta
__device__ __forceinline__ unsigned strip_mask(const float* __restrict__ h,
                                               int y, int x0, float theta){
    int yA = y > 0      ? y - 1 : 0;
    int yB = y < NH - 1 ? y + 1 : NH - 1;
    const float* r0 = h + yA * NW;
    const float* r1 = h + y  * NW;
    const float* r2 = h + yB * NW;
    float4 a0 = *(const float4*)(r0 + x0); float4 b0 = *(const float4*)(r0 + x0 + 4);
    float4 a1 = *(const float4*)(r1 + x0); float4 b1 = *(const float4*)(r1 + x0 + 4);
    float4 a2 = *(const float4*)(r2 + x0); float4 b2 = *(const float4*)(r2 + x0 + 4);
    float c[8] = {a1.x, a1.y, a1.z, a1.w, b1.x, b1.y, b1.z, b1.w};
    float vm[10];
    vm[1] = fmaxf(fmaxf(a0.x, a1.x), a2.x);
    vm[2] = fmaxf(fmaxf(a0.y, a1.y), a2.y);
    vm[3] = fmaxf(fmaxf(a0.z, a1.z), a2.z);
    vm[4] = fmaxf(fmaxf(a0.w, a1.w), a2.w);
    vm[5] = fmaxf(fmaxf(b0.x, b1.x), b2.x);
    vm[6] = fmaxf(fmaxf(b0.y, b1.y), b2.y);
    vm[7] = fmaxf(fmaxf(b0.z, b1.z), b2.z);
    vm[8] = fmaxf(fmaxf(b0.w, b1.w), b2.w);
    vm[0] = (x0 > 0)      ? fmaxf(fmaxf(r0[x0-1], r1[x0-1]), r2[x0-1]) : -1e30f;
    vm[9] = (x0 + 8 < NW) ? fmaxf(fmaxf(r0[x0+8], r1[x0+8]), r2[x0+8]) : -1e30f;
    unsigned msk = 0u;
    #pragma unroll
    for (int j = 0; j < 8; j++){
        float hm = fmaxf(fmaxf(vm[j], vm[j+1]), vm[j+2]);
        if (c[j] == hm && c[j] > theta) msk |= (1u << j);
    }
    return msk;
}

// unaggregated append (divergent-safe; used on rare paths)
__device__ __forceinline__ void verify_append(const float* __restrict__ h,
                                              int bc, int item, float theta){
    int y  = item / 40;
    int x0 = (item - y * 40) * 8;
    unsigned msk = strip_mask(h, y, x0, theta);
    if (msk){
        int pos = atomicAdd(&g_ccnt[bc], __popc(msk));
        int base = y * NW + x0;
        while (msk){
            int j = __ffs(msk) - 1; msk &= msk - 1;
            if (pos < GCAP)
                g_cand[(size_t)bc * GCAP + pos] =
                    ((ull)f2k(h[base + j]) << 32) | (unsigned)~(base + j);
            pos++;
        }
    }
}

__device__ __forceinline__ void inv3(const float* __restrict__ A, float* Ai){
    float a = A[0], b = A[1], c = A[2];
    float d = A[3], e = A[4], f = A[5];
    float g = A[6], h = A[7], i = A[8];
    float A00 = e*i - f*h, A01 = c*h - b*i, A02 = b*f - c*e;
    float A10 = f*g - d*i, A11 = a*i - c*g, A12 = c*d - a*f;
    float A20 = d*h - e*g, A21 = b*g - a*h, A22 = a*e - b*d;
    float r = 1.0f / (a*A00 + b*A10 + c*A20);
    Ai[0] = A00*r; Ai[1] = A01*r; Ai[2] = A02*r;
    Ai[3] = A10*r; Ai[4] = A11*r; Ai[5] = A12*r;
    Ai[6] = A20*r; Ai[7] = A21*r; Ai[8] = A22*r;
}

__device__ __forceinline__ float wrap_pi(float a){
    return a > PI_F ? a - 2.0f*PI_F : (a < -PI_F ? a + 2.0f*PI_F : a);
}

// ---------------------------------------------------------------------------
// K1: screen + verify. 576 CTAs x 256 thr = one full wave @ 4 CTAs/SM.
// Each sub-CTA screens 1280 strips (5/thread, batched coalesced loads),
// verifies flagged strips, appends survivors with ONE atomic per warp.
// ---------------------------------------------------------------------------
__global__ void __launch_bounds__(NT1, 4)
screen_kernel(const float* __restrict__ heat){
    __shared__ int flist[FCAP];
    __shared__ int fcnt;

    const int bx  = blockIdx.x;
    const int bc  = bx / SUBS;
    const int sub = bx - bc * SUBS;
    const float* __restrict__ h = heat + (size_t)bc * NHW;
    const int t = threadIdx.x;
    const int lane = t & 31;

    if (t == 0) fcnt = 0;
    __syncthreads();

    const int base = sub * SUBSTRIPS;

    // phase 1: batched loads, then reduce (keeps MLP high)
    float m8v[5];
    #pragma unroll
    for (int k = 0; k < 5; k++){
        int s = base + t + k * NT1;
        int y = s / 40;
        int x0 = (s - y * 40) * 8;
        const float* p = h + y * NW + x0;
        float4 a  = *(const float4*)p;
        float4 bv = *(const float4*)(p + 4);
        m8v[k] = fmaxf(max4(a), max4(bv));
    }
    // phase 2: flag + compact
    #pragma unroll
    for (int k = 0; k < 5; k++){
        bool flag = m8v[k] > THETA;
        unsigned bal = __ballot_sync(0xFFFFFFFFu, flag);
        if (bal){
            int ldr = __ffs(bal) - 1, bp = 0;
            if (lane == ldr) bp = atomicAdd(&fcnt, __popc(bal));
            bp = __shfl_sync(0xFFFFFFFFu, bp, ldr);
            if (flag){
                int pos = bp + __popc(bal & ((1u << lane) - 1u));
                int s = base + t + k * NT1;
                if (pos < FCAP) flist[pos] = s;
                else            verify_append(h, bc, s, THETA);   // overflow (rare)
            }
        }
    }
    __syncthreads();

    // phase 3: verify flagged strips; warp-aggregated global append
    int fc = min(fcnt, FCAP);
    int fcpad = (fc + NT1 - 1) & ~(NT1 - 1);
    for (int i = t; i < fcpad; i += NT1){
        unsigned msk = 0u; int sid = 0;
        if (i < fc){
            sid = flist[i];
            int y = sid / 40, x0 = (sid - y * 40) * 8;
            msk = strip_mask(h, y, x0, THETA);
        }
        int cnum = __popc(msk);
        int inc = cnum;
        #pragma unroll
        for (int d = 1; d < 32; d <<= 1){
            int v = __shfl_up_sync(0xFFFFFFFFu, inc, d);
            if (lane >= d) inc += v;
        }
        int tot = __shfl_sync(0xFFFFFFFFu, inc, 31);
        if (tot){
            int bp = 0;
            if (lane == 31) bp = atomicAdd(&g_ccnt[bc], tot);
            bp = __shfl_sync(0xFFFFFFFFu, bp, 31);
            int pos = bp + inc - cnum;
            int y = sid / 40, x0 = (sid - y * 40) * 8;
            int pbase = y * NW + x0;
            while (msk){
                int j = __ffs(msk) - 1; msk &= msk - 1;
                if (pos < GCAP)
                    g_cand[(size_t)bc * GCAP + pos] =
                        ((ull)f2k(h[pbase + j]) << 32) | (unsigned)~(pbase + j);
                pos++;
            }
        }
    }
}

// ---------------------------------------------------------------------------
// K2: one CTA per batch. Per-channel exact top-50 (rank) + 3-way merge
// (value-only, flat-position ties == lax.top_k stage 2) + gather + geometry.
// Fallbacks: n<50 -> unscreened rescan; n>CDIR -> radix-select. Resets
// counters at the end for graph replay.
// ---------------------------------------------------------------------------
__global__ void __launch_bounds__(NT2)
select_kernel(const float* __restrict__ heat,
              const float* __restrict__ regr,
              const float* __restrict__ calib,
              const float* __restrict__ trans,
              const float* __restrict__ dimref,
              float* __restrict__ out){
    __shared__ ull cbuf[NC][CDIR];
    __shared__ ull spk[NC*K_TOP];
    __shared__ ull rpk[K_TOP];
    __shared__ float sreg[K_TOP][13];
    __shared__ unsigned hist[256];
    __shared__ int s_mc[NC];
    __shared__ int s_n, scnt;
    __shared__ unsigned s_prefix;
    __shared__ int s_remaining, s_total;

    const int b = blockIdx.x;
    const int t = threadIdx.x;

    // ---- acquire candidates for each channel ----------------------------
    for (int c = 0; c < NC; c++){
        int bcc = b * NC + c;
        const float* __restrict__ h = heat + (size_t)bcc * NHW;
        if (t == 0) s_n = g_ccnt[bcc];
        __syncthreads();
        int n = s_n;

        if (n < K_TOP || n > GCAP){
            // guard: screened set provably complete iff 50<=n<=GCAP
            if (t == 0) atomicExch(&g_ccnt[bcc], 0);
            __syncthreads();
            for (int item = t; item < NSTRIPS; item += NT2)
                verify_append(h, bcc, item, -1e30f);
            __syncthreads();
            if (t == 0) s_n = g_ccnt[bcc];
            __syncthreads();
            n = min(s_n, GCAP);
        }

        const ull* gsrc = g_cand + (size_t)bcc * GCAP;
        if (n <= CDIR){
            for (int i = t; i < n; i += NT2) cbuf[c][i] = gsrc[i];
            if (t == 0) s_mc[c] = n;
        } else {
            // radix-select top>=50 into cbuf[c] (rare)
            if (t == 0){ scnt = 0; s_prefix = 0u; s_remaining = K_TOP; s_total = 0; }
            __syncthreads();
            unsigned prefix = 0u; int shift = 24;
            #pragma unroll 1
            for (int pass = 0; pass < 4; pass++){
                if (t < 256) hist[t] = 0u;
                __syncthreads();
                for (int j = t; j < n; j += NT2){
                    unsigned key = (unsigned)(gsrc[j] >> 32);
                    bool act = (pass == 0) || ((key >> (shift + 8)) == prefix);
                    if (act) atomicAdd(&hist[(key >> shift) & 255u], 1u);
                }
                __syncthreads();
                if (t == 0){
                    int rem = s_remaining, cum = 0, d = 255;
                    for (int dd = 255; dd >= 0; dd--){
                        cum += (int)hist[dd];
                        if (cum >= rem){ d = dd; break; }
                    }
                    int above = cum - (int)hist[d];
                    s_total     = (K_TOP - rem) + cum;
                    s_remaining = rem - above;
                    s_prefix    = (s_prefix << 8) | (unsigned)d;
                }
                __syncthreads();
                prefix = s_prefix;
                if (s_total <= SBUF || shift == 0) break;
                shift -= 8;
            }
            for (int j = t; j < n; j += NT2){
                ull p = gsrc[j];
                if (((unsigned)(p >> 32) >> shift) >= prefix){
                    int q = atomicAdd(&scnt, 1);
                    if (q < SBUF) cbuf[c][q] = p;
                }
            }
            __syncthreads();
            if (t == 0) s_mc[c] = min(scnt, SBUF);
        }
        __syncthreads();
    }

    // ---- per-channel exact rank -> spk (value desc, idx asc) ------------
    if (t < NC*K_TOP) spk[t] = ((ull)0x80000000u << 32) | 0xFFFFFFFFull;
    __syncthreads();
    {
        int m0 = s_mc[0], m1 = s_mc[1], m2 = s_mc[2];
        int M = m0 + m1 + m2;
        for (int q = t; q < M; q += NT2){
            int c, i;
            if (q < m0){ c = 0; i = q; }
            else if (q < m0 + m1){ c = 1; i = q - m0; }
            else { c = 2; i = q - m0 - m1; }
            int m = s_mc[c];
            ull mine = cbuf[c][i];
            int r = 0;
            for (int jj = 0; jj < m; jj++) r += (cbuf[c][jj] > mine);
            if (r < K_TOP) spk[c*K_TOP + r] = mine;
        }
    }
    __syncthreads();

    // ---- merge: rank on VALUE only; ties -> lower flat position ---------
    if (t < NC*K_TOP){
        ull mine = spk[t];
        unsigned mk = (unsigned)(mine >> 32);
        int r = 0;
        #pragma unroll 10
        for (int jj = 0; jj < NC*K_TOP; jj++){
            unsigned ok = (unsigned)(spk[jj] >> 32);
            r += (ok > mk) || (ok == mk && jj < t);
        }
        if (r < K_TOP){
            int cls = t / K_TOP;
            unsigned idx = ~((unsigned)mine);
            rpk[r] = ((ull)mk << 32) | ((unsigned)cls << 20) | idx;
        }
    }
    __syncthreads();

    // ---- cooperative gather: 600 loads, 3 independent rounds ------------
    #pragma unroll
    for (int rd = 0; rd < 3; rd++){
        int q = t + rd * NT2;
        if (q < K_TOP * 12){
            int det  = q / 12;
            int comp = q - det * 12;
            ull p = rpk[det];
            if (k2f((unsigned)(p >> 32)) > DET_TH)
                sreg[det][comp] = __ldg(regr + ((size_t)b * 12 + comp) * NHW
                                             + (int)(p & 0xFFFFFu));
        }
    }
    __syncthreads();

    // ---- geometry -------------------------------------------------------
    if (t < K_TOP){
        const int det = b * K_TOP + t;
        ull p = rpk[t];
        float score = k2f((unsigned)(p >> 32));
        float* o = out + (size_t)det * 14;

        if (!(score > DET_TH)){
            #pragma unroll
            for (int i = 0; i < 14; i++) o[i] = 0.0f;
        } else {
            int cls = (int)((p >> 20) & 3u);
            int hw  = (int)(p & 0xFFFFFu);
            float xs = (float)(hw % NW);
            float ys = (float)(hw / NW);

            float reg[12];
            #pragma unroll
            for (int r = 0; r < 12; r++) reg[r] = sreg[t][r];

            float Ti[9], Ki[9], Tm[9], Km[9];
            #pragma unroll
            for (int i = 0; i < 9; i++){ Tm[i] = __ldg(trans + b*9 + i); Km[i] = __ldg(calib + b*9 + i); }
            inv3(Tm, Ti);
            inv3(Km, Ki);

            float depth = reg[0] * 16.32f + 28.01f;
            float px = xs + reg[1], py = ys + reg[2];
            float t0 = (Ti[0]*px + Ti[1]*py + Ti[2]) * depth;
            float t1 = (Ti[3]*px + Ti[4]*py + Ti[5]) * depth;
            float t2 = (Ti[6]*px + Ti[7]*py + Ti[8]) * depth;
            float l0 = Ki[0]*t0 + Ki[1]*t1 + Ki[2]*t2;
            float l1 = Ki[3]*t0 + Ki[4]*t1 + Ki[5]*t2;
            float l2 = Ki[6]*t0 + Ki[7]*t1 + Ki[8]*t2;

            float d0 = expf(reg[3]) * __ldg(dimref + cls*3 + 0);
            float d1 = expf(reg[4]) * __ldg(dimref + cls*3 + 1);
            float d2 = expf(reg[5]) * __ldg(dimref + cls*3 + 2);
            l1 += d1 * 0.5f;

            float ray   = atanf(l0 / (l2 + 1e-7f));
            float alpha = atanf(reg[6] / (reg[7] + 1e-7f));
            alpha += (reg[7] >= 0.0f) ? -PI_F*0.5f : PI_F*0.5f;
            float roty = wrap_pi(alpha + ray);     // pre-wrap alpha, per ref
            alpha = wrap_pi(alpha);

            float cx = xs + reg[8], cy = ys + reg[9];
            float ltx = cx - reg[10]*0.5f, lty = cy - reg[11]*0.5f;
            float rbx = cx + reg[10]*0.5f, rby = cy + reg[11]*0.5f;
            float b0 = Ti[0]*ltx + Ti[1]*lty + Ti[2];
            float b1 = Ti[3]*ltx + Ti[4]*lty + Ti[5];
            float b2 = Ti[0]*rbx + Ti[1]*rby + Ti[2];
            float b3 = Ti[3]*rbx + Ti[4]*rby + Ti[5];

            o[0]  = (float)cls;
            o[1]  = alpha;
            o[2]  = b0; o[3] = b1; o[4] = b2; o[5] = b3;
            o[6]  = d1; o[7] = d2; o[8] = d0;      // roll(dims3d, -1)
            o[9]  = l0; o[10] = l1; o[11] = l2;
            o[12] = roty;
            o[13] = score;
        }
    }

    // reset this batch's channel counters for the next graph replay
    __syncthreads();
    if (t < NC) g_ccnt[b * NC + t] = 0;
}

// ---------------------------------------------------------------------------
extern "C" void kernel_launch(void* const* d_in, const int* in_sizes, int n_in,
                              void* d_out, int out_size){
    const float* heat   = (const float*)d_in[0];
    const float* regr   = (const float*)d_in[1];
    const float* calib  = (const float*)d_in[2];
    const float* trans  = (const float*)d_in[3];
    const float* dimref = (const float*)d_in[4];
    float* out = (float*)d_out;

    screen_kernel<<<NB * NC * SUBS, NT1>>>(heat);
    select_kernel<<<NB, NT2>>>(heat, regr, calib, trans, dimref, out);
}

// round 13
// speedup vs baseline: 1.7578x; 1.7578x over previous
#include <cuda_runtime.h>

#define NB 64
#define NC 3
#define NH 96
#define NW 320
#define NHW (NH*NW)
#define K_TOP 50
#define CAND_CAP 4608
#define DIRECT_MAX 1024
#define SBUF 512
#define FCAP 512
#define THETA 0.99f
#define DET_TH 0.25f
#define PI_F 3.14159265f
#define NSTRIPS (NH*(NW/8))   // 3840 strips of 8 pixels
#define NT 512

typedef unsigned long long ull;

// one packed u64 per (channel, rank): (f2k(value)<<32) | ~pixel_idx
__device__ ull g_pk[NB*NC*K_TOP];
// per-batch arrival counters (zero-init at load; each launch resets its own)
__device__ int g_bar[NB];

__device__ __forceinline__ unsigned f2k(float f){
    unsigned b = __float_as_uint(f);
    return (b & 0x80000000u) ? ~b : (b | 0x80000000u);
}
__device__ __forceinline__ float k2f(unsigned k){
    return (k & 0x80000000u) ? __uint_as_float(k ^ 0x80000000u) : __uint_as_float(~k);
}
__device__ __forceinline__ float max4(float4 v){
    return fmaxf(fmaxf(v.x, v.y), fmaxf(v.z, v.w));
}

// full 3x3 NMS test for one 8-pixel strip; bitmask of peaks > theta
__device__ __forceinline__ unsigned strip_mask(const float* __restrict__ h,
                                               int y, int x0, float theta){
    int yA = y > 0      ? y - 1 : 0;
    int yB = y < NH - 1 ? y + 1 : NH - 1;
    const float* r0 = h + yA * NW;
    const float* r1 = h + y  * NW;
    const float* r2 = h + yB * NW;
    float4 a0 = *(const float4*)(r0 + x0); float4 b0 = *(const float4*)(r0 + x0 + 4);
    float4 a1 = *(const float4*)(r1 + x0); float4 b1 = *(const float4*)(r1 + x0 + 4);
    float4 a2 = *(const float4*)(r2 + x0); float4 b2 = *(const float4*)(r2 + x0 + 4);
    float c[8] = {a1.x, a1.y, a1.z, a1.w, b1.x, b1.y, b1.z, b1.w};
    float vm[10];
    vm[1] = fmaxf(fmaxf(a0.x, a1.x), a2.x);
    vm[2] = fmaxf(fmaxf(a0.y, a1.y), a2.y);
    vm[3] = fmaxf(fmaxf(a0.z, a1.z), a2.z);
    vm[4] = fmaxf(fmaxf(a0.w, a1.w), a2.w);
    vm[5] = fmaxf(fmaxf(b0.x, b1.x), b2.x);
    vm[6] = fmaxf(fmaxf(b0.y, b1.y), b2.y);
    vm[7] = fmaxf(fmaxf(b0.z, b1.z), b2.z);
    vm[8] = fmaxf(fmaxf(b0.w, b1.w), b2.w);
    vm[0] = (x0 > 0)      ? fmaxf(fmaxf(r0[x0-1], r1[x0-1]), r2[x0-1]) : -1e30f;
    vm[9] = (x0 + 8 < NW) ? fmaxf(fmaxf(r0[x0+8], r1[x0+8]), r2[x0+8]) : -1e30f;
    unsigned msk = 0u;
    #pragma unroll
    for (int j = 0; j < 8; j++){
        float hm = fmaxf(fmaxf(vm[j], vm[j+1]), vm[j+2]);
        if (c[j] == hm && c[j] > theta) msk |= (1u << j);
    }
    return msk;
}

__device__ __forceinline__ void inv3(const float* __restrict__ A, float* Ai){
    float a = A[0], b = A[1], c = A[2];
    float d = A[3], e = A[4], f = A[5];
    float g = A[6], h = A[7], i = A[8];
    float A00 = e*i - f*h, A01 = c*h - b*i, A02 = b*f - c*e;
    float A10 = f*g - d*i, A11 = a*i - c*g, A12 = c*d - a*f;
    float A20 = d*h - e*g, A21 = b*g - a*h, A22 = a*e - b*d;
    float r = 1.0f / (a*A00 + b*A10 + c*A20);
    Ai[0] = A00*r; Ai[1] = A01*r; Ai[2] = A02*r;
    Ai[3] = A10*r; Ai[4] = A11*r; Ai[5] = A12*r;
    Ai[6] = A20*r; Ai[7] = A21*r; Ai[8] = A22*r;
}

__device__ __forceinline__ float wrap_pi(float a){
    return a > PI_F ? a - 2.0f*PI_F : (a < -PI_F ? a + 2.0f*PI_F : a);
}

// ---------------------------------------------------------------------------
// Fused kernel: one CTA per (batch, channel). 192 CTAs x 512 thr, 2 CTAs/SM
// -> ONE wave. A1: screen 8 strips/thread in 2 batches of 4 coalesced
// lane-per-strip loads (2 exposed DRAM trips). A2: verify flagged strips.
// Rank in smem -> g_pk. Last CTA per batch: merge + gather + geometry.
// ---------------------------------------------------------------------------
__global__ void __launch_bounds__(NT, 2)
postproc_kernel(const float* __restrict__ heat,
                const float* __restrict__ regr,
                const float* __restrict__ calib,
                const float* __restrict__ trans,
                const float* __restrict__ dimref,
                float* __restrict__ out){
    __shared__ ull      ck[CAND_CAP];
    __shared__ union { ull sk[SBUF]; int flist[FCAP]; } u;   // disjoint lifetimes
    __shared__ unsigned hist[256];
    __shared__ int cnt, scnt, fcnt, s_arrive;
    __shared__ unsigned s_prefix;
    __shared__ int s_remaining, s_total;
    __shared__ ull spk[NC*K_TOP];
    __shared__ ull rpk[K_TOP];            // (key<<32)|(cls<<20)|idx
    __shared__ float sreg[K_TOP][13];     // padded: conflict-free

    const int bc = blockIdx.x;            // b*NC + c
    const int b  = bc / NC;
    const float* __restrict__ h = heat + (size_t)bc * NHW;
    const int t = threadIdx.x;

    if (t == 0){ cnt = 0; scnt = 0; fcnt = 0; s_prefix = 0u; s_remaining = K_TOP; s_total = 0; }
    __syncthreads();

    // ---- A1: screen 8 strips/thread, 2 batches of 4 loads ---------------
    #pragma unroll
    for (int half = 0; half < 2; half++){
        float4 av[4], bv[4];
        int sid[4];
        #pragma unroll
        for (int k = 0; k < 4; k++){
            int s = t + (half * 4 + k) * NT;
            bool valid = (s < NSTRIPS);             // only last slot partial
            int sc = valid ? s : 0;
            sid[k] = valid ? s : -1;
            int y = sc / 40, x0 = (sc - y * 40) * 8;
            const float* p = h + y * NW + x0;
            av[k] = *(const float4*)p;
            bv[k] = *(const float4*)(p + 4);
        }
        #pragma unroll
        for (int k = 0; k < 4; k++){
            if (sid[k] >= 0){
                float m8 = fmaxf(max4(av[k]), max4(bv[k]));
                if (m8 > THETA){
                    int p = atomicAdd(&fcnt, 1);
                    if (p < FCAP) u.flist[p] = sid[k];
                }
            }
        }
    }
    __syncthreads();

    // ---- A2: heavy pass on flagged strips only --------------------------
    bool need_full = (fcnt > FCAP);
    if (!need_full){
        int fc = min(fcnt, FCAP);
        #pragma unroll 1
        for (int i = t; i < fc; i += NT){
            int item = u.flist[i];
            int y  = item / 40;
            int x0 = (item - y * 40) * 8;
            unsigned msk = strip_mask(h, y, x0, THETA);
            if (msk){
                int pos = atomicAdd(&cnt, __popc(msk));
                int base = y * NW + x0;
                while (msk){
                    int j = __ffs(msk) - 1; msk &= msk - 1;
                    if (pos < CAND_CAP)
                        ck[pos] = ((ull)f2k(h[base + j]) << 32) | (unsigned)~(base + j);
                    pos++;
                }
            }
        }
        __syncthreads();
        need_full = (cnt < K_TOP);   // screened set provably complete iff cnt>=50
    }

    // ---- fallback: full unscreened scan (correctness guard) -------------
    if (need_full){
        if (t == 0) cnt = 0;
        __syncthreads();
        #pragma unroll 1
        for (int item = t; item < NSTRIPS; item += NT){
            int y  = item / 40;
            int x0 = (item - y * 40) * 8;
            unsigned msk = strip_mask(h, y, x0, -1e30f);
            if (msk){
                int pos = atomicAdd(&cnt, __popc(msk));
                int base = y * NW + x0;
                while (msk){
                    int j = __ffs(msk) - 1; msk &= msk - 1;
                    if (pos < CAND_CAP)
                        ck[pos] = ((ull)f2k(h[base + j]) << 32) | (unsigned)~(base + j);
                    pos++;
                }
            }
        }
        __syncthreads();
    }

    int n = min(cnt, CAND_CAP);
    const ull* src = ck;
    int m = n;

    if (n > DIRECT_MAX){
        // ---- radix-select fallback (rare) -------------------------------
        unsigned prefix = 0u;
        int shift = 24;
        #pragma unroll 1
        for (int pass = 0; pass < 4; pass++){
            if (t < 256) hist[t] = 0u;
            __syncthreads();
            for (int j = t; j < n; j += NT){
                unsigned key = (unsigned)(ck[j] >> 32);
                bool act = (pass == 0) || ((key >> (shift + 8)) == prefix);
                if (act) atomicAdd(&hist[(key >> shift) & 255u], 1u);
            }
            __syncthreads();
            if (t == 0){
                int rem = s_remaining;
                int cum = 0, d = 255;
                for (int dd = 255; dd >= 0; dd--){
                    cum += (int)hist[dd];
                    if (cum >= rem){ d = dd; break; }
                }
                int above_inc = cum - (int)hist[d];
                s_total     = (K_TOP - rem) + cum;
                s_remaining = rem - above_inc;
                s_prefix    = (s_prefix << 8) | (unsigned)d;
            }
            __syncthreads();
            prefix = s_prefix;
            if (s_total <= SBUF || shift == 0) break;
            shift -= 8;
        }
        for (int j = t; j < n; j += NT){
            ull p = ck[j];
            if (((unsigned)(p >> 32) >> shift) >= prefix){
                int q = atomicAdd(&scnt, 1);
                if (q < SBUF) u.sk[q] = p;
            }
        }
        __syncthreads();
        src = u.sk; m = min(scnt, SBUF);
    }

    // pad slots, then exact parallel rank (value desc, idx asc) -> g_pk
    if (t < K_TOP) g_pk[bc * K_TOP + t] = ((ull)0x80000000u << 32) | 0xFFFFFFFFull;
    __syncthreads();
    for (int i = t; i < m; i += NT){
        ull mine = src[i];
        int r = 0;
        for (int jj = 0; jj < m; jj++) r += (src[jj] > mine);   // smem broadcast
        if (r < K_TOP) g_pk[bc * K_TOP + r] = mine;
    }

    // ---- Stage 2 handoff: last CTA of the batch merges ------------------
    __syncthreads();
    __threadfence();                              // publish g_pk slice
    if (t == 0) s_arrive = atomicAdd(&g_bar[b], 1);
    __syncthreads();
    if (s_arrive != NC - 1) return;               // not the last arriver
    __threadfence();                              // see peers' g_pk writes

    if (t < NC*K_TOP) spk[t] = g_pk[b * NC * K_TOP + t];
    __syncthreads();

    // rank on VALUE ONLY; ties -> lower flat position (lax.top_k stage 2)
    if (t < NC*K_TOP){
        ull mine = spk[t];
        unsigned mk = (unsigned)(mine >> 32);
        int r = 0;
        #pragma unroll 10
        for (int jj = 0; jj < NC*K_TOP; jj++){
            unsigned ok = (unsigned)(spk[jj] >> 32);
            r += (ok > mk) || (ok == mk && jj < t);
        }
        if (r < K_TOP){
            int cls = t / K_TOP;
            unsigned idx = ~((unsigned)mine);
            rpk[r] = ((ull)mk << 32) | ((unsigned)cls << 20) | idx;
        }
    }
    __syncthreads();

    // cooperative gather: 600 loads, two independent rounds over 512 thr
    {
        int q0 = t, q1 = t + NT;
        int det0 = q0 / 12, comp0 = q0 - det0 * 12;
        ull p0 = rpk[det0];
        bool g0 = (k2f((unsigned)(p0 >> 32)) > DET_TH);
        int det1 = 0, comp1 = 0; ull p1 = 0; bool g1 = false;
        if (q1 < K_TOP * 12){
            det1 = q1 / 12; comp1 = q1 - det1 * 12;
            p1 = rpk[det1];
            g1 = (k2f((unsigned)(p1 >> 32)) > DET_TH);
        }
        float x0v = 0.f, x1v = 0.f;
        if (g0) x0v = __ldg(regr + ((size_t)b * 12 + comp0) * NHW + (int)(p0 & 0xFFFFFu));
        if (g1) x1v = __ldg(regr + ((size_t)b * 12 + comp1) * NHW + (int)(p1 & 0xFFFFFu));
        if (g0) sreg[det0][comp0] = x0v;
        if (g1) sreg[det1][comp1] = x1v;
    }
    __syncthreads();

    if (t < K_TOP){
        const int det = b * K_TOP + t;
        ull p = rpk[t];
        float score = k2f((unsigned)(p >> 32));
        float* o = out + (size_t)det * 14;

        if (!(score > DET_TH)){
            #pragma unroll
            for (int i = 0; i < 14; i++) o[i] = 0.0f;
        } else {
            int cls = (int)((p >> 20) & 3u);
            int hw  = (int)(p & 0xFFFFFu);
            float xs = (float)(hw % NW);
            float ys = (float)(hw / NW);

            float reg[12];
            #pragma unroll
            for (int r = 0; r < 12; r++) reg[r] = sreg[t][r];

            float Ti[9], Ki[9], Tm[9], Km[9];
            #pragma unroll
            for (int i = 0; i < 9; i++){ Tm[i] = __ldg(trans + b*9 + i); Km[i] = __ldg(calib + b*9 + i); }
            inv3(Tm, Ti);
            inv3(Km, Ki);

            float depth = reg[0] * 16.32f + 28.01f;
            float px = xs + reg[1], py = ys + reg[2];
            float t0 = (Ti[0]*px + Ti[1]*py + Ti[2]) * depth;
            float t1 = (Ti[3]*px + Ti[4]*py + Ti[5]) * depth;
            float t2 = (Ti[6]*px + Ti[7]*py + Ti[8]) * depth;
            float l0 = Ki[0]*t0 + Ki[1]*t1 + Ki[2]*t2;
            float l1 = Ki[3]*t0 + Ki[4]*t1 + Ki[5]*t2;
            float l2 = Ki[6]*t0 + Ki[7]*t1 + Ki[8]*t2;

            float d0 = expf(reg[3]) * __ldg(dimref + cls*3 + 0);
            float d1 = expf(reg[4]) * __ldg(dimref + cls*3 + 1);
            float d2 = expf(reg[5]) * __ldg(dimref + cls*3 + 2);
            l1 += d1 * 0.5f;

            float ray   = atanf(l0 / (l2 + 1e-7f));
            float alpha = atanf(reg[6] / (reg[7] + 1e-7f));
            alpha += (reg[7] >= 0.0f) ? -PI_F*0.5f : PI_F*0.5f;
            float roty = wrap_pi(alpha + ray);     // pre-wrap alpha, per ref
            alpha = wrap_pi(alpha);

            float cx = xs + reg[8], cy = ys + reg[9];
            float ltx = cx - reg[10]*0.5f, lty = cy - reg[11]*0.5f;
            float rbx = cx + reg[10]*0.5f, rby = cy + reg[11]*0.5f;
            float b0 = Ti[0]*ltx + Ti[1]*lty + Ti[2];
            float b1 = Ti[3]*ltx + Ti[4]*lty + Ti[5];
            float b2 = Ti[0]*rbx + Ti[1]*rby + Ti[2];
            float b3 = Ti[3]*rbx + Ti[4]*rby + Ti[5];

            o[0]  = (float)cls;
            o[1]  = alpha;
            o[2]  = b0; o[3] = b1; o[4] = b2; o[5] = b3;
            o[6]  = d1; o[7] = d2; o[8] = d0;      // roll(dims3d, -1)
            o[9]  = l0; o[10] = l1; o[11] = l2;
            o[12] = roty;
            o[13] = score;
        }
    }

    // reset the batch counter for the next (graph-replayed) launch
    if (t == 0) g_bar[b] = 0;
}

// ---------------------------------------------------------------------------
extern "C" void kernel_launch(void* const* d_in, const int* in_sizes, int n_in,
                              void* d_out, int out_size){
    const float* heat   = (const float*)d_in[0];
    const float* regr   = (const float*)d_in[1];
    const float* calib  = (const float*)d_in[2];
    const float* trans  = (const float*)d_in[3];
    const float* dimref = (const float*)d_in[4];
    float* out = (float*)d_out;

    postproc_kernel<<<NB * NC, NT>>>(heat, regr, calib, trans, dimref, out);
}